// round 16
// baseline (speedup 1.0000x reference)
#include <cuda_runtime.h>

#define NN 50000
#define NE 800000
#define NG 128
#define HH 70
#define HP 72
#define IND 32

// ---------------- scratch (device globals; zero-initialized) ----------------
__device__ float d_h[NN*HP];
__device__ float d_h2[NN*HP];
__device__ float d_hnew[NN*HP];
__device__ float d_Ah[NN*HP];
__device__ float d_Bh[NN*HP];
__device__ float d_Dh[NN*HP];
__device__ float d_Eh2[NN*HP];
__device__ float d_e[NE*HH];        // 224 MB
__device__ float d_enew[NE*HH];     // 224 MB
__device__ int   d_cnt[NN];
__device__ int   d_cnt2[NN];
__device__ int   d_ptr[NN+1];
__device__ int   d_eidx[NE];
__device__ int   d_esrc[NE];
__device__ int   d_bs[256];
__device__ int   d_bsx[256];
__device__ float d_partE[12500*140];
__device__ float d_partH[6250*140];
__device__ float d_part2E[64*140];
__device__ float d_part2H[64*140];
__device__ int   d_flagE, d_flagH;
__device__ float d_scaleE[HH], d_shiftE[HH];
__device__ float d_scaleH[HH], d_shiftH[HH];
__device__ float d_weC[HP], d_beC[HP];

// ---------------- packed-fp32 helpers ---------------------------------------
__device__ __forceinline__ unsigned long long bc2(float w){
    unsigned long long r;
    asm("mov.b64 %0, {%1, %1};" : "=l"(r) : "f"(w));
    return r;
}
__device__ __forceinline__ void fma2(float2 &c, float2 a, unsigned long long bw){
    unsigned long long ca = *(unsigned long long*)&a;
    unsigned long long cc = *(unsigned long long*)&c;
    asm("fma.rn.f32x2 %0, %1, %2, %0;" : "+l"(cc) : "l"(ca), "l"(bw));
    c = *(float2*)&cc;
}
__device__ __forceinline__ float sigm(float x){
    float t;
    asm("tanh.approx.f32 %0, %1;" : "=f"(t) : "f"(x*0.5f));
    return fmaf(t, 0.5f, 0.5f);
}

// ---------------- CSR build (deterministic) --------------------------------
__global__ void k_zero_cnt(){
    int i = blockIdx.x*blockDim.x + threadIdx.x;
    if(i < NN){ d_cnt[i]=0; d_cnt2[i]=0; }
}

__global__ void k_hist(const int* __restrict__ dst){
    int i = blockIdx.x*blockDim.x + threadIdx.x;
    if(i < NE) atomicAdd(&d_cnt[dst[i]], 1);
}

__global__ void k_scanA(){
    __shared__ int sm[256];
    int t = threadIdx.x, i = blockIdx.x*256 + t;
    sm[t] = (i < NN) ? d_cnt[i] : 0;
    __syncthreads();
    for(int off=128; off>0; off>>=1){ if(t<off) sm[t]+=sm[t+off]; __syncthreads(); }
    if(t==0) d_bs[blockIdx.x] = sm[0];
}
__global__ void k_scanB(int nb){
    __shared__ int sm[256];
    int t = threadIdx.x;
    int v = (t < nb) ? d_bs[t] : 0;
    sm[t] = v; __syncthreads();
    for(int off=1; off<256; off<<=1){
        int x = (t>=off) ? sm[t-off] : 0;
        __syncthreads(); sm[t] += x; __syncthreads();
    }
    d_bsx[t] = sm[t] - v;
}
__global__ void k_scanC(){
    __shared__ int sm[256];
    int t = threadIdx.x, b = blockIdx.x, i = b*256 + t;
    int v = (i < NN) ? d_cnt[i] : 0;
    sm[t] = v; __syncthreads();
    for(int off=1; off<256; off<<=1){
        int x = (t>=off) ? sm[t-off] : 0;
        __syncthreads(); sm[t] += x; __syncthreads();
    }
    if(i < NN) d_ptr[i+1] = d_bsx[b] + sm[t];
    if(i == 0) d_ptr[0] = 0;
}

__global__ void k_scatter(const int* __restrict__ dst){
    int i = blockIdx.x*blockDim.x + threadIdx.x;
    if(i < NE){
        int d = dst[i];
        int pos = d_ptr[d] + atomicAdd(&d_cnt2[d], 1);
        d_eidx[pos] = i;
    }
}

__global__ void k_sortadj(const int* __restrict__ src){
    int n = blockIdx.x*blockDim.x + threadIdx.x;
    if(n >= NN) return;
    int lo = d_ptr[n], hi = d_ptr[n+1];
    for(int i=lo+1; i<hi; ++i){
        int v = d_eidx[i];
        int j = i-1;
        while(j>=lo && d_eidx[j] > v){ d_eidx[j+1]=d_eidx[j]; j--; }
        d_eidx[j+1]=v;
    }
    for(int i=lo; i<hi; ++i) d_esrc[i] = src[d_eidx[i]];
}

// ---------------- embeddings / rank-1 precompute ----------------------------
__global__ void k_emb_h(const float* __restrict__ nf, const float* __restrict__ w,
                        const float* __restrict__ b){
    __shared__ __align__(16) float xs[16*IND];
    __shared__ __align__(16) float Ws[IND*HP];
    __shared__ float sb[HH];
    int t = threadIdx.x; int base = blockIdx.x*16;
    for(int idx=t; idx<16*IND; idx+=280) xs[idx] = nf[base*IND + idx];
    for(int idx=t; idx<IND*HH; idx+=280){
        int k = idx/HH, j = idx - k*HH;
        Ws[k*HP + j] = w[idx];
    }
    if(t < HH) sb[t] = b[t];
    __syncthreads();
    int c = t % HH, rg = t / HH;
    float acc[4] = {0.f,0.f,0.f,0.f};
    for(int k4=0; k4<IND; k4+=4){
        float w0 = Ws[(k4+0)*HP+c], w1v = Ws[(k4+1)*HP+c];
        float w2v = Ws[(k4+2)*HP+c], w3v = Ws[(k4+3)*HP+c];
        #pragma unroll
        for(int r=0; r<4; r++){
            const float4 xv = *(const float4*)&xs[(rg*4+r)*IND + k4];
            acc[r] = fmaf(xv.x,w0, fmaf(xv.y,w1v, fmaf(xv.z,w2v, fmaf(xv.w,w3v, acc[r]))));
        }
    }
    float bias = sb[c];
    #pragma unroll
    for(int r=0; r<4; r++)
        d_h[(base + rg*4 + r)*HP + c] = acc[r] + bias;
    if(t < 32){
        int r = t >> 1, p = t & 1;
        d_h[(base + r)*HP + HH + p] = 0.f;
    }
}

// weC = we @ Cw0, beC = be @ Cw0 + Cb0
__global__ void k_wC(const float* __restrict__ we, const float* __restrict__ be,
                     const float* __restrict__ Cw, const float* __restrict__ Cb){
    int j = threadIdx.x;
    if(j >= HP) return;
    if(j < HH){
        float sw = 0.f, sbv = 0.f;
        for(int k=0; k<HH; k++){
            float c = Cw[k*HH + j];
            sw  = fmaf(we[k], c, sw);
            sbv = fmaf(be[k], c, sbv);
        }
        d_weC[j] = sw; d_beC[j] = sbv + Cb[j];
    } else { d_weC[j] = 0.f; d_beC[j] = 0.f; }
}

// ---------------- per-layer node linear (FFMA2, pair-packed rows) -----------
// hsel: 0 -> hin=d_h, hout=d_h2 ; 1 -> hin=d_h2, hout=d_h.
// fuse: stage h = hin + relu(bn_h(hnew)) ; wr: write staged h to hout.
__global__ void __launch_bounds__(140) k_node2(
        const float* __restrict__ W1, const float* __restrict__ b1,
        const float* __restrict__ W2, const float* __restrict__ b2,
        int sel, int fuse, int hsel, int wr){
    __shared__ __align__(16) float Ws[HH*140];
    __shared__ __align__(16) float hsp[16*HP*2];
    __shared__ float sSc[HH], sSh[HH];
    int t = threadIdx.x; int base = blockIdx.x*32;
    const float* hin = hsel ? d_h2 : d_h;
    float*       hout = hsel ? d_h : d_h2;
    for(int idx=t; idx<HH*140; idx+=140){
        int k = idx/140, c = idx - k*140;
        Ws[idx] = (c < HH) ? W1[k*HH + c] : W2[k*HH + (c-HH)];
    }
    if(fuse && t < HH){ sSc[t] = d_scaleH[t]; sSh[t] = d_shiftH[t]; }
    __syncthreads();
    for(int idx=t; idx<32*36; idx+=140){
        int r = idx/36, j2 = idx - r*36;
        int rp = r >> 1, par = r & 1;
        int row = base + r;
        if(j2 < 35){
            int j = j2*2;
            float2 val = make_float2(0.f, 0.f);
            if(row < NN){
                int g = row*HP + j;
                val = *(const float2*)&hin[g];
                if(fuse){
                    float2 hn = *(const float2*)&d_hnew[g];
                    float y0 = fmaf(sSc[j],   hn.x, sSh[j]);
                    float y1 = fmaf(sSc[j+1], hn.y, sSh[j+1]);
                    val.x += fmaxf(y0, 0.f); val.y += fmaxf(y1, 0.f);
                    if(wr) *(float2*)&hout[g] = val;
                }
            }
            hsp[(rp*HP + j)*2 + par]   = val.x;
            hsp[(rp*HP + j+1)*2 + par] = val.y;
        } else {
            hsp[(rp*HP + 70)*2 + par] = 0.f;
            hsp[(rp*HP + 71)*2 + par] = 0.f;
        }
    }
    __syncthreads();
    int cq = t % 35, rg = t / 35;
    int c0 = cq*4;
    float2 acc[4][4];
    #pragma unroll
    for(int rp=0;rp<4;rp++)
        #pragma unroll
        for(int cc=0;cc<4;cc++) acc[rp][cc] = make_float2(0.f,0.f);
    const float* hb = &hsp[(rg*4)*(HP*2)];
    #pragma unroll 5
    for(int k=0; k<HH; k+=2){
        float4 w0 = *(const float4*)&Ws[k*140 + c0];
        float4 w1 = *(const float4*)&Ws[(k+1)*140 + c0];
        unsigned long long b00=bc2(w0.x), b01=bc2(w0.y), b02=bc2(w0.z), b03=bc2(w0.w);
        unsigned long long b10=bc2(w1.x), b11=bc2(w1.y), b12=bc2(w1.z), b13=bc2(w1.w);
        #pragma unroll
        for(int rp=0;rp<4;rp++){
            float4 ev = *(const float4*)&hb[rp*(HP*2) + k*2];
            float2 e0 = make_float2(ev.x, ev.y);
            float2 e1 = make_float2(ev.z, ev.w);
            fma2(acc[rp][0], e0, b00); fma2(acc[rp][0], e1, b10);
            fma2(acc[rp][1], e0, b01); fma2(acc[rp][1], e1, b11);
            fma2(acc[rp][2], e0, b02); fma2(acc[rp][2], e1, b12);
            fma2(acc[rp][3], e0, b03); fma2(acc[rp][3], e1, b13);
        }
    }
    #pragma unroll
    for(int cc=0; cc<4; cc++){
        int c = c0 + cc;
        int m = (c >= HH) ? 1 : 0;
        int j = c - HH*m;
        const float* bb = m ? b2 : b1;
        float* outp = sel ? (m ? d_Eh2 : d_Dh) : (m ? d_Bh : d_Ah);
        float bias = __ldg(&bb[j]);
        #pragma unroll
        for(int rp=0;rp<4;rp++){
            int r0 = base + rg*8 + 2*rp;
            if(r0 < NN)   outp[r0*HP + j]     = acc[rp][cc].x + bias;
            if(r0+1 < NN) outp[(r0+1)*HP + j] = acc[rp][cc].y + bias;
        }
    }
}

// ---------------- edge kernel (FFMA2 pair-packed, fused residual-in) --------
// mode 1: e_prev = rank-1 (ef*we+be); mode 2: e_prev = d_e.
__global__ void __launch_bounds__(144) k_edge(
        const float* __restrict__ Cw, const float* __restrict__ Cb,
        const int* __restrict__ src, const int* __restrict__ dst,
        const float* __restrict__ snorm_e,
        const float* __restrict__ ef, const float* __restrict__ we,
        const float* __restrict__ be,
        int mode, int write_e){
    __shared__ __align__(16) float Ws[HP*HP];
    __shared__ __align__(16) float esp[32*HP*2];
    __shared__ float sb[HP];
    __shared__ int   ssrc[64], sdst[64];
    __shared__ float ssn[64], sef[64];
    __shared__ float sE[HH], sH[HH];
    __shared__ float swe[HP], sbe[HP];
    int t = threadIdx.x; int base = blockIdx.x*64;

    for(int idx=t; idx<HP*HP; idx+=144){
        int k = idx/HP, j = idx - k*HP;
        Ws[idx] = (k < HH && j < HH) ? Cw[k*HH + j] : 0.f;
    }
    if(t < 64){
        int ei = base + t;
        ssrc[t] = src[ei]*HP; sdst[t] = dst[ei]*HP; ssn[t] = snorm_e[ei];
        if(mode == 1) sef[t] = ef[ei];
    }
    if(t < HP) sb[t] = (t < HH) ? Cb[t] : 0.f;
    if(t < HH){ sE[t] = d_scaleE[t]; sH[t] = d_shiftE[t]; }
    if(mode == 1 && t < HP){
        swe[t] = (t < HH) ? we[t] : 0.f;
        sbe[t] = (t < HH) ? be[t] : 0.f;
    }
    __syncthreads();

    for(int idx=t; idx<64*36; idx+=144){
        int r = idx/36, j2 = idx - r*36;
        int rp = r >> 1, par = r & 1;
        if(j2 < 35){
            int j = j2*2;
            int g = (base+r)*HH + j;
            float2 en = *(const float2*)&d_enew[g];
            float2 ep;
            if(mode == 1){
                float fe = sef[r];
                ep.x = fmaf(fe, swe[j],   sbe[j]);
                ep.y = fmaf(fe, swe[j+1], sbe[j+1]);
            } else {
                ep = *(const float2*)&d_e[g];
            }
            float snr = ssn[r];
            float y0 = fmaf(sE[j],   en.x*snr, sH[j]);
            float y1 = fmaf(sE[j+1], en.y*snr, sH[j+1]);
            float2 val;
            val.x = ep.x + fmaxf(y0, 0.f);
            val.y = ep.y + fmaxf(y1, 0.f);
            if(write_e) *(float2*)&d_e[g] = val;
            esp[(rp*HP + j)*2 + par]   = val.x;
            esp[(rp*HP + j+1)*2 + par] = val.y;
        } else {
            esp[(rp*HP + 70)*2 + par] = 0.f;
            esp[(rp*HP + 71)*2 + par] = 0.f;
        }
    }
    __syncthreads();

    int cq = t % 18, rg = t / 18;
    int c0 = cq*4;
    float2 acc[4][4];
    #pragma unroll
    for(int rp=0;rp<4;rp++)
        #pragma unroll
        for(int cc=0;cc<4;cc++) acc[rp][cc] = make_float2(0.f,0.f);
    const float* eb = &esp[(rg*4)*(HP*2)];
    #pragma unroll 6
    for(int k=0; k<HP; k+=2){
        float4 w0 = *(const float4*)&Ws[k*HP + c0];
        float4 w1 = *(const float4*)&Ws[(k+1)*HP + c0];
        unsigned long long b00=bc2(w0.x), b01=bc2(w0.y), b02=bc2(w0.z), b03=bc2(w0.w);
        unsigned long long b10=bc2(w1.x), b11=bc2(w1.y), b12=bc2(w1.z), b13=bc2(w1.w);
        #pragma unroll
        for(int rp=0;rp<4;rp++){
            float4 ev = *(const float4*)&eb[rp*(HP*2) + k*2];
            float2 e0 = make_float2(ev.x, ev.y);
            float2 e1 = make_float2(ev.z, ev.w);
            fma2(acc[rp][0], e0, b00); fma2(acc[rp][0], e1, b10);
            fma2(acc[rp][1], e0, b01); fma2(acc[rp][1], e1, b11);
            fma2(acc[rp][2], e0, b02); fma2(acc[rp][2], e1, b12);
            fma2(acc[rp][3], e0, b03); fma2(acc[rp][3], e1, b13);
        }
    }

    float4 sbv = *(const float4*)&sb[c0];
    bool full = (c0 < 68);
    float s1a[4] = {0.f,0.f,0.f,0.f}, s2a[4] = {0.f,0.f,0.f,0.f};
    #pragma unroll
    for(int rp=0;rp<4;rp++){
        int r0 = rg*8 + 2*rp, r1 = r0+1;
        float4 dv0 = *(const float4*)&d_Dh[ssrc[r0] + c0];
        float4 ev0 = *(const float4*)&d_Eh2[sdst[r0] + c0];
        float4 dv1 = *(const float4*)&d_Dh[ssrc[r1] + c0];
        float4 ev1 = *(const float4*)&d_Eh2[sdst[r1] + c0];
        float v00 = acc[rp][0].x + sbv.x + dv0.x + ev0.x;
        float v01 = acc[rp][1].x + sbv.y + dv0.y + ev0.y;
        float v02 = acc[rp][2].x + sbv.z + dv0.z + ev0.z;
        float v03 = acc[rp][3].x + sbv.w + dv0.w + ev0.w;
        float v10 = acc[rp][0].y + sbv.x + dv1.x + ev1.x;
        float v11 = acc[rp][1].y + sbv.y + dv1.y + ev1.y;
        float v12 = acc[rp][2].y + sbv.z + dv1.z + ev1.z;
        float v13 = acc[rp][3].y + sbv.w + dv1.w + ev1.w;
        int g0 = (base+r0)*HH + c0, g1 = (base+r1)*HH + c0;
        *(float2*)&d_enew[g0] = make_float2(v00, v01);
        *(float2*)&d_enew[g1] = make_float2(v10, v11);
        if(full){
            *(float2*)&d_enew[g0+2] = make_float2(v02, v03);
            *(float2*)&d_enew[g1+2] = make_float2(v12, v13);
        }
        float sn0 = ssn[r0], sn1 = ssn[r1], x;
        x=v00*sn0; s1a[0]+=x; s2a[0]=fmaf(x,x,s2a[0]);
        x=v10*sn1; s1a[0]+=x; s2a[0]=fmaf(x,x,s2a[0]);
        x=v01*sn0; s1a[1]+=x; s2a[1]=fmaf(x,x,s2a[1]);
        x=v11*sn1; s1a[1]+=x; s2a[1]=fmaf(x,x,s2a[1]);
        if(full){
            x=v02*sn0; s1a[2]+=x; s2a[2]=fmaf(x,x,s2a[2]);
            x=v12*sn1; s1a[2]+=x; s2a[2]=fmaf(x,x,s2a[2]);
            x=v03*sn0; s1a[3]+=x; s2a[3]=fmaf(x,x,s2a[3]);
            x=v13*sn1; s1a[3]+=x; s2a[3]=fmaf(x,x,s2a[3]);
        }
    }
    __syncthreads();
    float* sred = esp;
    #pragma unroll
    for(int cc=0;cc<4;cc++){
        sred[rg*144 + c0 + cc]      = s1a[cc];
        sred[rg*144 + 72 + c0 + cc] = s2a[cc];
    }
    __syncthreads();
    if(t < 140){
        int slot = (t < HH) ? t : (t - HH + HP);
        float p = 0.f;
        #pragma unroll
        for(int g=0; g<8; g++) p += sred[g*144 + slot];
        d_partE[blockIdx.x*140 + t] = p;
    }
}

// ---------------- layer-0 edge (rank-1, elementwise) ------------------------
__global__ void __launch_bounds__(144) k_edge0(
        const int* __restrict__ src, const int* __restrict__ dst,
        const float* __restrict__ snorm_e, const float* __restrict__ ef){
    __shared__ float sweC[HP], sbeC[HP];
    __shared__ int   ssrc[64], sdst[64];
    __shared__ float ssn[64], sef[64];
    __shared__ float sred[8*144];
    int t = threadIdx.x; int base = blockIdx.x*64;
    if(t < 64){
        int ei = base + t;
        ssrc[t] = src[ei]*HP; sdst[t] = dst[ei]*HP;
        ssn[t] = snorm_e[ei]; sef[t] = ef[ei];
    }
    if(t < HP){ sweC[t] = d_weC[t]; sbeC[t] = d_beC[t]; }
    __syncthreads();
    int cq = t % 18, rg = t / 18;
    int c0 = cq*4;
    float4 wv = *(const float4*)&sweC[c0];
    float4 bv = *(const float4*)&sbeC[c0];
    bool full = (c0 < 68);
    float s1a[4] = {0.f,0.f,0.f,0.f}, s2a[4] = {0.f,0.f,0.f,0.f};
    #pragma unroll
    for(int r=0; r<8; r++){
        int row = rg*8 + r;
        float fe = sef[row];
        float4 dv  = *(const float4*)&d_Dh[ssrc[row] + c0];
        float4 evv = *(const float4*)&d_Eh2[sdst[row] + c0];
        float v0 = fmaf(fe, wv.x, bv.x) + dv.x + evv.x;
        float v1 = fmaf(fe, wv.y, bv.y) + dv.y + evv.y;
        float v2 = fmaf(fe, wv.z, bv.z) + dv.z + evv.z;
        float v3 = fmaf(fe, wv.w, bv.w) + dv.w + evv.w;
        int g = (base+row)*HH + c0;
        *(float2*)&d_enew[g] = make_float2(v0, v1);
        if(full) *(float2*)&d_enew[g+2] = make_float2(v2, v3);
        float snr = ssn[row], x;
        x=v0*snr; s1a[0]+=x; s2a[0]=fmaf(x,x,s2a[0]);
        x=v1*snr; s1a[1]+=x; s2a[1]=fmaf(x,x,s2a[1]);
        if(full){
            x=v2*snr; s1a[2]+=x; s2a[2]=fmaf(x,x,s2a[2]);
            x=v3*snr; s1a[3]+=x; s2a[3]=fmaf(x,x,s2a[3]);
        }
    }
    __syncthreads();
    #pragma unroll
    for(int cc=0;cc<4;cc++){
        sred[rg*144 + c0 + cc]      = s1a[cc];
        sred[rg*144 + 72 + c0 + cc] = s2a[cc];
    }
    __syncthreads();
    if(t < 140){
        int slot = (t < HH) ? t : (t - HH + HP);
        float p = 0.f;
        #pragma unroll
        for(int g=0; g<8; g++) p += sred[g*144 + slot];
        d_partE[blockIdx.x*140 + t] = p;
    }
}

// ---------------- fused BN reduce: 64 blocks, last block finalizes ----------
__global__ void k_redfused(const float* __restrict__ gamma, const float* __restrict__ beta,
                           float invM, int which, int nparts, int chunk){
    float* part  = which ? d_partH  : d_partE;
    float* part2 = which ? d_part2H : d_part2E;
    int*   flag  = which ? &d_flagH : &d_flagE;
    __shared__ float ssum[140];
    __shared__ int s_last;
    int b = blockIdx.x, t = threadIdx.x;
    if(t < 140){
        int lo = b*chunk, hi = min(lo + chunk, nparts);
        float s = 0.f;
        for(int p=lo; p<hi; p++) s += part[p*140 + t];
        part2[b*140 + t] = s;
    }
    __threadfence();
    __syncthreads();
    if(t == 0){
        int v = atomicAdd(flag, 1);
        s_last = (v == 63);
    }
    __syncthreads();
    if(!s_last) return;
    if(t < 140){
        float s = 0.f;
        #pragma unroll 4
        for(int bb=0; bb<64; bb++) s += part2[bb*140 + t];
        ssum[t] = s;
    }
    __syncthreads();
    if(t < HH){
        float mean = ssum[t]*invM;
        float var  = ssum[70+t]*invM - mean*mean;
        float inv  = rsqrtf(var + 1e-5f);
        float sc   = gamma[t]*inv;
        float sh   = beta[t] - mean*sc;
        if(which){ d_scaleH[t]=sc; d_shiftH[t]=sh; }
        else     { d_scaleE[t]=sc; d_shiftE[t]=sh; }
    }
    if(t == 0) *flag = 0;
}

// ---------------- aggregation (warp per node, unroll-2 gather chains) -------
__global__ void k_agg(const float* __restrict__ snorm_n){
    __shared__ float sm1[8*HH];
    int wi = threadIdx.x >> 5;
    int lane = threadIdx.x & 31;
    int n = blockIdx.x*8 + wi;
    int c0=lane, c1=lane+32, c2=lane+64;
    bool has2 = (c2 < HH);
    float num0=0.f,num1=0.f,num2=0.f,den0=0.f,den1=0.f,den2=0.f;
    int s0 = d_ptr[n], s1 = d_ptr[n+1];
    int j = s0;
    for(; j+1 < s1; j += 2){
        int eidA = d_eidx[j],   eidB = d_eidx[j+1];
        int spA  = d_esrc[j]*HP,  spB = d_esrc[j+1]*HP;
        int epA  = eidA*HH,       epB = eidB*HH;
        float eA0 = d_enew[epA+c0], eA1 = d_enew[epA+c1];
        float eB0 = d_enew[epB+c0], eB1 = d_enew[epB+c1];
        float bA0 = d_Bh[spA+c0],   bA1 = d_Bh[spA+c1];
        float bB0 = d_Bh[spB+c0],   bB1 = d_Bh[spB+c1];
        float eA2 = 0.f, eB2 = 0.f, bA2 = 0.f, bB2 = 0.f;
        if(has2){
            eA2 = d_enew[epA+c2]; eB2 = d_enew[epB+c2];
            bA2 = d_Bh[spA+c2];   bB2 = d_Bh[spB+c2];
        }
        float gA0 = sigm(eA0), gA1 = sigm(eA1);
        float gB0 = sigm(eB0), gB1 = sigm(eB1);
        num0 = fmaf(gA0,bA0,num0); den0 += gA0;
        num0 = fmaf(gB0,bB0,num0); den0 += gB0;
        num1 = fmaf(gA1,bA1,num1); den1 += gA1;
        num1 = fmaf(gB1,bB1,num1); den1 += gB1;
        if(has2){
            float gA2 = sigm(eA2), gB2 = sigm(eB2);
            num2 = fmaf(gA2,bA2,num2); den2 += gA2;
            num2 = fmaf(gB2,bB2,num2); den2 += gB2;
        }
    }
    if(j < s1){
        int eid = d_eidx[j];
        int ep = eid*HH;
        int sp = d_esrc[j]*HP;
        float e0 = d_enew[ep+c0], e1 = d_enew[ep+c1];
        float b0 = d_Bh[sp+c0],   b1 = d_Bh[sp+c1];
        float g0 = sigm(e0);
        float g1 = sigm(e1);
        num0 = fmaf(g0,b0,num0); den0 += g0;
        num1 = fmaf(g1,b1,num1); den1 += g1;
        if(has2){
            float e2 = d_enew[ep+c2], b2v = d_Bh[sp+c2];
            float g2 = sigm(e2);
            num2 = fmaf(g2,b2v,num2); den2 += g2;
        }
    }
    float snv = snorm_n[n];
    int base = n*HP;
    float x0 = (d_Ah[base+c0] + __fdividef(num0, den0+1e-6f))*snv;
    float x1v= (d_Ah[base+c1] + __fdividef(num1, den1+1e-6f))*snv;
    d_hnew[base+c0]=x0; d_hnew[base+c1]=x1v;
    sm1[wi*HH+c0]=x0; sm1[wi*HH+c1]=x1v;
    if(has2){
        float x2v = (d_Ah[base+c2] + __fdividef(num2, den2+1e-6f))*snv;
        d_hnew[base+c2]=x2v;
        sm1[wi*HH+c2]=x2v;
    }
    __syncthreads();
    int t = threadIdx.x;
    if(t < HH){
        float p1=0.f, p2=0.f;
        #pragma unroll
        for(int k=0;k<8;k++){ float v=sm1[k*HH+t]; p1+=v; p2=fmaf(v,v,p2); }
        d_partH[blockIdx.x*140 + t]      = p1;
        d_partH[blockIdx.x*140 + 70 + t] = p2;
    }
}

// ---------------- readout + final h update + MLP (fused) --------------------
__global__ void k_readout(const int* __restrict__ gids,
                          const float* __restrict__ w0, const float* __restrict__ b0,
                          const float* __restrict__ w1, const float* __restrict__ b1,
                          const float* __restrict__ w2, const float* __restrict__ b2,
                          float* __restrict__ out, int hsel){
    int g = blockIdx.x;
    __shared__ int sse[2];
    __shared__ float sSc[HH], sSh[HH];
    __shared__ float red[210];
    __shared__ float hg[HH];
    __shared__ float x1[35];
    __shared__ float x2[17];
    const float* hin = hsel ? d_h2 : d_h;
    int t = threadIdx.x;
    if(t < 2){
        int target = g + t;
        int lo = 0, hi = NN;
        if(target >= NG) lo = NN;
        else {
            while(lo < hi){
                int mid = (lo+hi)>>1;
                if(gids[mid] < target) lo = mid+1; else hi = mid;
            }
        }
        sse[t] = lo;
    }
    if(t < HH){ sSc[t] = d_scaleH[t]; sSh[t] = d_shiftH[t]; }
    __syncthreads();
    int s = sse[0], e = sse[1];
    int cnt = e - s;
    if(t < 210){
        int c = t % HH, gr = t / HH;
        float sc = sSc[c], sh = sSh[c];
        float ps = 0.f;
        for(int n=s+gr; n<e; n+=3){
            float hv = hin[n*HP + c];
            float hn = d_hnew[n*HP + c];
            ps += hv + fmaxf(fmaf(sc, hn, sh), 0.f);
        }
        red[t] = ps;
    }
    __syncthreads();
    if(t < HH) hg[t] = (red[t] + red[70+t] + red[140+t]) / fmaxf((float)cnt, 1.f);
    __syncthreads();
    if(t < 35){
        float a = b0[t];
        for(int k=0;k<HH;k++) a = fmaf(hg[k], w0[k*35+t], a);
        x1[t] = fmaxf(a, 0.f);
    }
    __syncthreads();
    if(t < 17){
        float a = b1[t];
        for(int k=0;k<35;k++) a = fmaf(x1[k], w1[k*17+t], a);
        x2[t] = fmaxf(a, 0.f);
    }
    __syncthreads();
    if(t < 10){
        float a = b2[t];
        for(int k=0;k<17;k++) a = fmaf(x2[k], w2[k*10+t], a);
        out[g*10 + t] = a;
    }
}

// ---------------- host orchestration (multi-stream overlap) -----------------
extern "C" void kernel_launch(void* const* d_in, const int* in_sizes, int n_in,
                              void* d_out, int out_size){
    const float* nodes_feat = (const float*)d_in[0];
    const float* edges_feat = (const float*)d_in[1];
    const float* snorm_n    = (const float*)d_in[2];
    const float* snorm_e    = (const float*)d_in[3];
    const float* emb_h_w    = (const float*)d_in[4];
    const float* emb_h_b    = (const float*)d_in[5];
    const float* emb_e_w    = (const float*)d_in[6];
    const float* emb_e_b    = (const float*)d_in[7];
    const float* Aw = (const float*)d_in[8];  const float* Ab = (const float*)d_in[9];
    const float* Bw = (const float*)d_in[10]; const float* Bb = (const float*)d_in[11];
    const float* Cw = (const float*)d_in[12]; const float* Cb = (const float*)d_in[13];
    const float* Dw = (const float*)d_in[14]; const float* Db = (const float*)d_in[15];
    const float* Ew = (const float*)d_in[16]; const float* Eb = (const float*)d_in[17];
    const float* bn_h_g = (const float*)d_in[18]; const float* bn_h_b = (const float*)d_in[19];
    const float* bn_e_g = (const float*)d_in[20]; const float* bn_e_b = (const float*)d_in[21];
    const float* w0 = (const float*)d_in[22]; const float* b0 = (const float*)d_in[23];
    const float* w1 = (const float*)d_in[24]; const float* b1 = (const float*)d_in[25];
    const float* w2 = (const float*)d_in[26]; const float* b2 = (const float*)d_in[27];
    const int* src  = (const int*)d_in[28];
    const int* dst  = (const int*)d_in[29];
    const int* gids = (const int*)d_in[30];
    float* out = (float*)d_out;

    int nb = (NN+255)/256;
    const int EPARTS = NE/64;            // 12500
    const int HPARTS = NN/8;             // 6250
    const int ECHUNK = (EPARTS+63)/64;   // 196
    const int HCHUNK = (HPARTS+63)/64;   // 98

    // streams/events created ONCE (first call = correctness run, before the
    // harness's pre-capture memory baseline). Handle cache only.
    static cudaStream_t sA = nullptr, sB = nullptr, sC = nullptr;
    static cudaEvent_t evRoot, evEmb, evCSR, evEdge[3], evE[3], evH[4], evC[4];
    if(sA == nullptr){
        cudaStreamCreateWithFlags(&sA, cudaStreamNonBlocking);
        cudaStreamCreateWithFlags(&sB, cudaStreamNonBlocking);
        cudaStreamCreateWithFlags(&sC, cudaStreamNonBlocking);
        cudaEventCreateWithFlags(&evRoot, cudaEventDisableTiming);
        cudaEventCreateWithFlags(&evEmb,  cudaEventDisableTiming);
        cudaEventCreateWithFlags(&evCSR,  cudaEventDisableTiming);
        for(int i=0;i<3;i++){
            cudaEventCreateWithFlags(&evEdge[i], cudaEventDisableTiming);
            cudaEventCreateWithFlags(&evE[i],    cudaEventDisableTiming);
        }
        for(int i=0;i<4;i++){
            cudaEventCreateWithFlags(&evH[i], cudaEventDisableTiming);
            cudaEventCreateWithFlags(&evC[i], cudaEventDisableTiming);
        }
    }

    cudaEventRecord(evRoot, 0);

    // main: embedding + layer-0 A/B GEMM; DE GEMM concurrently on sC.
    k_emb_h<<<NN/16, 280>>>(nodes_feat, emb_h_w, emb_h_b);              // 0
    cudaEventRecord(evEmb, 0);
    k_node2<<<(NN+31)/32, 140>>>(Aw, Ab, Bw, Bb, 0, 0, 0, 0);           // 1
    k_wC<<<1, 72>>>(emb_e_w, emb_e_b, Cw, Cb);                          // 2
    cudaStreamWaitEvent(sC, evEmb, 0);
    k_node2<<<(NN+31)/32, 140, 0, sC>>>(Dw, Db, Ew, Eb, 1, 0, 0, 0);    // 3 <- ncu
    cudaEventRecord(evC[0], sC);

    // CSR build concurrently on sA (needed only by k_agg)
    cudaStreamWaitEvent(sA, evRoot, 0);
    k_zero_cnt<<<(NN+255)/256, 256, 0, sA>>>();
    k_hist<<<(NE+255)/256, 256, 0, sA>>>(dst);
    k_scanA<<<nb, 256, 0, sA>>>();
    k_scanB<<<1, 256, 0, sA>>>(nb);
    k_scanC<<<nb, 256, 0, sA>>>();
    k_scatter<<<(NE+255)/256, 256, 0, sA>>>(dst);
    k_sortadj<<<(NN+255)/256, 256, 0, sA>>>(src);
    cudaEventRecord(evCSR, sA);

    for(int l=0; l<4; l++){
        size_t wo = (size_t)l*HH*HH, bo = (size_t)l*HH;
        // h buffer track: h1->d_h2, h2->d_h, h3->d_h2
        int hs = (l==2) ? 1 : 0;
        if(l > 0){
            k_node2<<<(NN+31)/32, 140>>>(Aw+wo, Ab+bo, Bw+wo, Bb+bo, 0, 1, hs, 1);
            cudaStreamWaitEvent(sC, evH[l-1], 0);
            k_node2<<<(NN+31)/32, 140, 0, sC>>>(Dw+wo, Db+bo, Ew+wo, Eb+bo, 1, 1, hs, 0);
            cudaEventRecord(evC[l], sC);
            cudaStreamWaitEvent(0, evC[l], 0);
            cudaStreamWaitEvent(0, evE[l-1], 0);
            k_edge<<<NE/64, 144>>>(Cw+wo, Cb+bo, src, dst, snorm_e,
                                   edges_feat, emb_e_w, emb_e_b,
                                   (l==1) ? 1 : 2, (l<3) ? 1 : 0);
        } else {
            cudaStreamWaitEvent(0, evC[0], 0);
            k_edge0<<<NE/64, 144>>>(src, dst, snorm_e, edges_feat);
        }
        if(l < 3){
            cudaEventRecord(evEdge[l], 0);
            cudaStreamWaitEvent(sB, evEdge[l], 0);
            k_redfused<<<64, 160, 0, sB>>>(bn_e_g+bo, bn_e_b+bo,
                                           1.f/(float)NE, 0, EPARTS, ECHUNK);
            cudaEventRecord(evE[l], sB);
        }
        if(l == 0) cudaStreamWaitEvent(0, evCSR, 0);
        k_agg<<<NN/8, 256>>>(snorm_n);
        k_redfused<<<64, 160>>>(bn_h_g+bo, bn_h_b+bo,
                                1.f/(float)NN, 1, HPARTS, HCHUNK);
        cudaEventRecord(evH[l], 0);
    }

    k_readout<<<NG, 256>>>(gids, w0, b0, w1, b1, w2, b2, out, 1);
}